// round 14
// baseline (speedup 1.0000x reference)
#include <cuda_runtime.h>
#include <cuda_fp16.h>
#include <cstdint>

// Problem constants
#define T_LEN 512
#define BATCH 32
#define DIM   512   // D == H
#define G4    2048  // 4*H
#define NCTA_DIR 32 // recurrence CTAs per direction (16 H-cols each)
#define HCOLS 16
#define NREC  64            // recurrence CTAs total
#define NWORK 84            // GEMM worker CTAs
#define NGRID (NREC + NWORK)

// Scratch
__device__ float g_xpre[(size_t)2 * T_LEN * G4 * BATCH]; // [dir][t][g][b]
// quarter-granularity step counters: [dir][quarter][t]  (separate lines per quarter)
__device__ int   g_qsync[2 * 4 * T_LEN];
__device__ int   g_xready[2 * T_LEN];                    // x_pre tile counters (full=16)
__device__ int   g_splitdone[1];

// fp16 split scratch for phase-1 GEMM: x hi/lo, W single
__device__ __half g_xhi[(size_t)16384 * 512];
__device__ __half g_xlo[(size_t)16384 * 512];
__device__ __half g_wf [(size_t)4096 * 512];

// h history: SINGLE fp16 plane [dir][t][b][512]
__device__ __half g_hf[(size_t)2 * T_LEN * BATCH * DIM];

__device__ __forceinline__ uint32_t smem_to_u32(const void* p) {
    uint32_t a;
    asm("{ .reg .u64 t; cvta.to.shared.u64 t, %1; cvt.u32.u64 %0, t; }" : "=r"(a) : "l"(p));
    return a;
}

#define CP_ASYNC16(dst, src) \
    asm volatile("cp.async.cg.shared.global [%0], [%1], 16;" :: "r"(dst), "l"(src) : "memory")
#define CP_COMMIT() asm volatile("cp.async.commit_group;" ::: "memory")
#define CP_WAIT2()  asm volatile("cp.async.wait_group 2;" ::: "memory")
#define CP_WAIT1()  asm volatile("cp.async.wait_group 1;" ::: "memory")
#define CP_WAIT0()  asm volatile("cp.async.wait_group 0;" ::: "memory")

#define LDMATRIX_X4(r0, r1, r2, r3, addr) \
    asm volatile("ldmatrix.sync.aligned.m8n8.x4.shared.b16 {%0,%1,%2,%3}, [%4];" \
        : "=r"(r0), "=r"(r1), "=r"(r2), "=r"(r3) : "r"(addr))
#define LDMATRIX_X2(r0, r1, addr) \
    asm volatile("ldmatrix.sync.aligned.m8n8.x2.shared.b16 {%0,%1}, [%2];" \
        : "=r"(r0), "=r"(r1) : "r"(addr))

#define MMA_F16(d, a, b) \
    asm volatile("mma.sync.aligned.m16n8k16.row.col.f32.f16.f16.f32 " \
        "{%0,%1,%2,%3}, {%4,%5,%6,%7}, {%8,%9}, {%0,%1,%2,%3};" \
        : "+f"((d)[0]), "+f"((d)[1]), "+f"((d)[2]), "+f"((d)[3]) \
        : "r"((a)[0]), "r"((a)[1]), "r"((a)[2]), "r"((a)[3]), "r"((b)[0]), "r"((b)[1]))

__device__ __forceinline__ uint32_t pack_f16(float a, float b) {
    uint32_t r;
    asm("cvt.rn.f16x2.f32 %0, %1, %2;" : "=r"(r) : "f"(b), "f"(a));
    return r;
}

__device__ __forceinline__ int ld_acquire(const int* p) {
    int v;
    asm volatile("ld.acquire.gpu.global.b32 %0, [%1];" : "=r"(v) : "l"(p) : "memory");
    return v;
}

// ---------------------------------------------------------------------------
__global__ void init_sync_kernel() {
    int i = blockIdx.x * blockDim.x + threadIdx.x;
    if (i < 2 * 4 * T_LEN) g_qsync[i] = 0;
    if (i < 2 * T_LEN) g_xready[i] = 0;
    if (i == 0) g_splitdone[0] = 0;
}

// ---------------------------------------------------------------------------
// GEMM tile constants
// ---------------------------------------------------------------------------
#define KC1 32
#define RPAD1 40
#define ARR1 (128 * RPAD1 * 2)
#define STAGE1 (3 * ARR1)
#define NCHUNK1 16

// Recurrence smem layout
#define KPAD 520
#define WF_OFF  0
#define HF_OFF  (64 * KPAD * 2)                 // 66560
#define KGB_OFF (HF_OFF + 32 * KPAD * 2)        // 99840
#define XPS_OFF (KGB_OFF + 4 * 64 * 33 * 4)     // 133632
#define SMEM_TOTAL (XPS_OFF + 64 * 36 * 4)      // 142848

// ---------------------------------------------------------------------------
// GEMM worker body: first fused split/cvt, then tiles in time-priority order.
// ---------------------------------------------------------------------------
__device__ void gemm_worker(char* smem, const float* __restrict__ x,
                            const float* __restrict__ Wih,
                            const float* __restrict__ bih,
                            const float* __restrict__ bhh, int worker)
{
    const uint32_t sb = smem_to_u32(smem);
    const int tid  = threadIdx.x;
    const int wid  = tid >> 5;
    const int lane = tid & 31;
    const int wg   = wid >> 1;
    const int wm   = wid & 1;
    const int grp  = lane >> 2;
    const int tig  = lane & 3;
    const int lrow = tid >> 1;

    // ---- fused split phase: x -> hi/lo fp16, Wih -> fp16 ----
    {
        const int gtid = worker * 256 + tid;
        const int nthr = NWORK * 256;
        const float4* x4 = (const float4*)x;
        const int nx4 = (16384 * 512) / 4;
        for (int i = gtid; i < nx4; i += nthr) {
            float4 v = x4[i];
            float f0 = __half2float(__float2half_rn(v.x));
            float f1 = __half2float(__float2half_rn(v.y));
            float f2 = __half2float(__float2half_rn(v.z));
            float f3 = __half2float(__float2half_rn(v.w));
            ((uint32_t*)g_xhi)[i * 2]     = pack_f16(f0, f1);
            ((uint32_t*)g_xhi)[i * 2 + 1] = pack_f16(f2, f3);
            ((uint32_t*)g_xlo)[i * 2]     = pack_f16(v.x - f0, v.y - f1);
            ((uint32_t*)g_xlo)[i * 2 + 1] = pack_f16(v.z - f2, v.w - f3);
        }
        const float4* w4 = (const float4*)Wih;
        const int nw4 = (4096 * 512) / 4;
        for (int i = gtid; i < nw4; i += nthr) {
            float4 v = w4[i];
            ((uint32_t*)g_wf)[i * 2]     = pack_f16(v.x, v.y);
            ((uint32_t*)g_wf)[i * 2 + 1] = pack_f16(v.z, v.w);
        }
        __threadfence();
        __syncthreads();
        if (tid == 0) atomicAdd(&g_splitdone[0], 1);
        while (ld_acquire(&g_splitdone[0]) < NWORK) { }
    }

    const uint32_t lm_row  = (uint32_t)(lane & 15);
    const uint32_t lm_colb = (uint32_t)(lane >> 4) * 16;

    for (int idx = worker; idx < 4096; idx += NWORK) {
        const int pair = idx >> 5;     // 0..127
        const int j    = idx & 31;     // 0..31
        const int gt   = j;            // g-tile 0..31 (dir = gt>>4)
        const int mt   = (j < 16) ? pair : (127 - pair);
        const int g0   = gt * 128;
        const int m0   = mt * 128;
        const int dir  = gt >> 4;

        const __half* gsrc[3] = {
            g_wf  + (size_t)(g0 + lrow) * 512,
            g_xhi + (size_t)(m0 + lrow) * 512,
            g_xlo + (size_t)(m0 + lrow) * 512
        };

        auto issue_chunk = [&](int kc) {
            const uint32_t stb = sb + (kc & 3) * STAGE1;
#pragma unroll
            for (int arr = 0; arr < 3; arr++) {
#pragma unroll
                for (int i = 0; i < 2; i++) {
                    int seg = (tid & 1) * 2 + i;
                    CP_ASYNC16(stb + arr * ARR1 + lrow * (RPAD1 * 2) + seg * 16,
                               gsrc[arr] + kc * KC1 + seg * 8);
                }
            }
            CP_COMMIT();
        };

        float acc[2][8][4];
#pragma unroll
        for (int mtt = 0; mtt < 2; mtt++)
#pragma unroll
            for (int nt = 0; nt < 8; nt++)
#pragma unroll
                for (int r = 0; r < 4; r++) acc[mtt][nt][r] = 0.f;

        issue_chunk(0);
        issue_chunk(1);
        issue_chunk(2);

        for (int kc = 0; kc < NCHUNK1; kc++) {
            const uint32_t stb = sb + (kc & 3) * STAGE1;
            CP_WAIT2();
            __syncthreads();

            const uint32_t AF  = stb;
            const uint32_t BHI = stb + ARR1;
            const uint32_t BLO = stb + 2 * ARR1;

#pragma unroll
            for (int kk = 0; kk < 2; kk++) {
                const uint32_t kb = lm_colb + kk * 32;

                uint32_t af[2][4], bb[4][4];
#pragma unroll
                for (int mtt = 0; mtt < 2; mtt++) {
                    uint32_t aoff = (wg * 32 + mtt * 16 + lm_row) * (RPAD1 * 2) + kb;
                    LDMATRIX_X4(af[mtt][0], af[mtt][1], af[mtt][2], af[mtt][3], AF + aoff);
                }
#pragma unroll
                for (int nt2 = 0; nt2 < 4; nt2++) {
                    uint32_t boff = (wm * 64 + nt2 * 16 + lm_row) * (RPAD1 * 2) + kb;
                    LDMATRIX_X4(bb[nt2][0], bb[nt2][1], bb[nt2][2], bb[nt2][3], BHI + boff);
                }
#pragma unroll
                for (int mtt = 0; mtt < 2; mtt++)
#pragma unroll
                    for (int nt = 0; nt < 8; nt++) {
                        uint32_t bfrag[2] = { bb[nt >> 1][nt & 1], bb[nt >> 1][(nt & 1) + 2] };
                        MMA_F16(acc[mtt][nt], af[mtt], bfrag);
                    }
#pragma unroll
                for (int nt2 = 0; nt2 < 4; nt2++) {
                    uint32_t boff = (wm * 64 + nt2 * 16 + lm_row) * (RPAD1 * 2) + kb;
                    LDMATRIX_X4(bb[nt2][0], bb[nt2][1], bb[nt2][2], bb[nt2][3], BLO + boff);
                }
#pragma unroll
                for (int mtt = 0; mtt < 2; mtt++)
#pragma unroll
                    for (int nt = 0; nt < 8; nt++) {
                        uint32_t bfrag[2] = { bb[nt >> 1][nt & 1], bb[nt >> 1][(nt & 1) + 2] };
                        MMA_F16(acc[mtt][nt], af[mtt], bfrag);
                    }
            }
            __syncthreads();
            if (kc + 3 < NCHUNK1) issue_chunk(kc + 3);
        }

        // epilogue: +bias, transposed scatter
        float bias[2][2];
        float* rowp[2][2];
#pragma unroll
        for (int mtt = 0; mtt < 2; mtt++)
#pragma unroll
            for (int hf = 0; hf < 2; hf++) {
                int g = g0 + wg * 32 + mtt * 16 + hf * 8 + grp;
                bias[mtt][hf] = bih[g] + bhh[g];
                int d = g >> 11, gp = g & 2047;
                rowp[mtt][hf] = g_xpre + ((size_t)d * T_LEN) * (G4 * BATCH) + (size_t)gp * BATCH;
            }
#pragma unroll
        for (int mtt = 0; mtt < 2; mtt++)
#pragma unroll
            for (int nt = 0; nt < 8; nt++) {
                int m = m0 + wm * 64 + nt * 8 + 2 * tig;
                int t = m >> 5, b = m & 31;
                size_t toff = (size_t)t * (G4 * BATCH) + b;
                float2 v0 = { acc[mtt][nt][0] + bias[mtt][0], acc[mtt][nt][1] + bias[mtt][0] };
                float2 v1 = { acc[mtt][nt][2] + bias[mtt][1], acc[mtt][nt][3] + bias[mtt][1] };
                *(float2*)(rowp[mtt][0] + toff) = v0;
                *(float2*)(rowp[mtt][1] + toff) = v1;
            }

        // signal the 4 timesteps this m-tile covers for this dir
        __threadfence();
        __syncthreads();
        if (tid < 4)
            atomicAdd(&g_xready[dir * T_LEN + mt * 4 + tid], 1);
    }
}

// ---------------------------------------------------------------------------
// Recurrence body with quarter-granularity acquire.
// ---------------------------------------------------------------------------
__device__ void rec_body(char* smraw,
                         const float* __restrict__ h0,
                         const float* __restrict__ c0,
                         const float* __restrict__ Whh,
                         float* __restrict__ out,
                         float* __restrict__ hout,
                         float* __restrict__ cout, int cta)
{
    const uint32_t sb = smem_to_u32(smraw);
    float* kgb = (float*)(smraw + KGB_OFF);
    float* xps = (float*)(smraw + XPS_OFF);
    uint32_t* Wf32 = (uint32_t*)(smraw + WF_OFF);
    uint32_t* Hf32 = (uint32_t*)(smraw + HF_OFF);

    const int dir  = cta >> 5;
    const int slot = cta & (NCTA_DIR - 1);
    const int j0   = slot * HCOLS;
    const int tid  = threadIdx.x;
    const int lane = tid & 31;
    const int wid  = tid >> 5;
    const int mhalf = wid >> 2;
    const int kg    = wid & 3;
    const int m0w   = mhalf * 16;

    // quarter this CTA's h slice belongs to
    const int myq = slot >> 3;
    int* my_rel = &g_qsync[(dir * 4 + myq) * T_LEN];
    const int* my_acq = &g_qsync[(dir * 4 + kg) * T_LEN];

    // ---- convert W_hh slice (64 local gate rows x 512) into smem fp16 ----
    {
        int lr = tid >> 2, seg = tid & 3;
        int gr = (lr >> 4) * DIM + j0 + (lr & 15);
        const float4* src = (const float4*)(Whh + ((size_t)dir * G4 + gr) * DIM + seg * 128);
        uint32_t* dst = Wf32 + ((lr * KPAD + seg * 128) >> 1);
#pragma unroll
        for (int i = 0; i < 32; i++) {
            float4 v = src[i];
            dst[i * 2]     = pack_f16(v.x, v.y);
            dst[i * 2 + 1] = pack_f16(v.z, v.w);
        }
    }
    float c_reg[2];
#pragma unroll
    for (int e = 0; e < 2; e++) {
        int cell = tid + e * 256;
        int b = cell >> 4, cc = cell & 15;
        c_reg[e] = c0[((size_t)dir * BATCH + b) * DIM + j0 + cc];
    }
    __syncthreads();

    // ---- preload W fragments (step-invariant): bw[nt][ks][2], 128 regs ----
    uint32_t bw[8][8][2];
    {
        const uint32_t brow = (uint32_t)(lane & 7);
        const uint32_t bcol = (uint32_t)((lane >> 3) & 1) * 16;
#pragma unroll
        for (int nt = 0; nt < 8; nt++)
#pragma unroll
            for (int ks = 0; ks < 8; ks++) {
                uint32_t off = (nt * 8 + brow) * (KPAD * 2) + kg * 256 + ks * 32 + bcol;
                LDMATRIX_X2(bw[nt][ks][0], bw[nt][ks][1], sb + WF_OFF + off);
            }
    }

    const uint32_t arow_off = (uint32_t)(m0w + (lane & 15)) * (KPAD * 2)
                            + (uint32_t)kg * 256 + (uint32_t)(lane >> 4) * 16;

    const int grp = lane >> 2;
    const int tig = lane & 3;

    for (int s = 0; s < T_LEN; s++) {
        const int t = dir ? (T_LEN - 1 - s) : s;

        // wait until x_pre[dir][t] fully produced, then prefetch slice
        {
            const int* xf = &g_xready[dir * T_LEN + t];
            while (ld_acquire(xf) < 16) { }
            int lr = tid >> 2, seg = tid & 3;
            int gp = (lr >> 4) * DIM + j0 + (lr & 15);
            const float* src = g_xpre + (size_t)dir * ((size_t)T_LEN * G4 * BATCH)
                             + (size_t)t * (G4 * BATCH) + (size_t)gp * BATCH + seg * 8;
            uint32_t d = sb + XPS_OFF + (uint32_t)(lr * 144 + seg * 32);
            CP_ASYNC16(d, src);
            CP_ASYNC16(d + 16, src + 4);
            CP_COMMIT();
        }

        if (s == 0) {
            const float4* h0p = (const float4*)(h0 + (size_t)dir * BATCH * DIM);
#pragma unroll
            for (int it = 0; it < 16; it++) {
                int idx = tid + it * 256;
                int b = idx >> 7, c4 = (idx & 127) * 4;
                float4 v = h0p[idx];
                int u = (b * KPAD + c4) >> 1;
                Hf32[u]     = pack_f16(v.x, v.y);
                Hf32[u + 1] = pack_f16(v.z, v.w);
            }
            __syncthreads();
            CP_COMMIT();
            CP_COMMIT();
        } else {
            // per-warp quarter acquire: warp kg waits for its 8 producers only
            while (ld_acquire(my_acq + (s - 1)) < 8) { }
            const int tp = dir ? (t + 1) : (t - 1);
            const __half* hf = g_hf + (size_t)(dir * T_LEN + tp) * (BATCH * DIM);
#pragma unroll
            for (int it = 0; it < 4; it++) {
                int u = lane + it * 32;
                int r = u >> 3, sg = u & 7;
                int row = m0w + r;
                size_t goff = (size_t)row * DIM + kg * 128 + sg * 8;
                uint32_t doff = (uint32_t)(row * KPAD + kg * 128 + sg * 8) * 2;
                CP_ASYNC16(sb + HF_OFF + doff, hf + goff);
            }
            CP_COMMIT();
#pragma unroll
            for (int it = 0; it < 4; it++) {
                int u = lane + it * 32;
                int r = u >> 3, sg = 8 + (u & 7);
                int row = m0w + r;
                size_t goff = (size_t)row * DIM + kg * 128 + sg * 8;
                uint32_t doff = (uint32_t)(row * KPAD + kg * 128 + sg * 8) * 2;
                CP_ASYNC16(sb + HF_OFF + doff, hf + goff);
            }
            CP_COMMIT();
        }

        // ---- MMA: h @ W^T, single pass, pipelined over k-halves ----
        float acc[8][4];
#pragma unroll
        for (int nt = 0; nt < 8; nt++)
#pragma unroll
            for (int r = 0; r < 4; r++) acc[nt][r] = 0.f;

        CP_WAIT1();
#pragma unroll
        for (int ks = 0; ks < 4; ks++) {
            uint32_t a_f[4];
            LDMATRIX_X4(a_f[0], a_f[1], a_f[2], a_f[3], sb + HF_OFF + arow_off + ks * 32);
#pragma unroll
            for (int nt = 0; nt < 8; nt++)
                MMA_F16(acc[nt], a_f, bw[nt][ks]);
        }
        CP_WAIT0();
#pragma unroll
        for (int ks = 4; ks < 8; ks++) {
            uint32_t a_f[4];
            LDMATRIX_X4(a_f[0], a_f[1], a_f[2], a_f[3], sb + HF_OFF + arow_off + ks * 32);
#pragma unroll
            for (int nt = 0; nt < 8; nt++)
                MMA_F16(acc[nt], a_f, bw[nt][ks]);
        }

        // scatter partials to kgb[kg][n][b]
        {
            float* kb = kgb + kg * (64 * 33);
            int b1 = m0w + grp, b2 = b1 + 8;
#pragma unroll
            for (int nt = 0; nt < 8; nt++) {
                int na = nt * 8 + 2 * tig;
                kb[na * 33 + b1]       = acc[nt][0];
                kb[(na + 1) * 33 + b1] = acc[nt][1];
                kb[na * 33 + b2]       = acc[nt][2];
                kb[(na + 1) * 33 + b2] = acc[nt][3];
            }
        }
        __syncthreads();

        // ---- LSTM update: 2 cells per thread; reduce 4 k-partials ----
        float h_val[2], c_new[2];
#pragma unroll
        for (int e = 0; e < 2; e++) {
            int cell = tid + e * 256;
            int b = cell >> 4, cc = cell & 15;
            float xi = xps[cc * 36 + b];
            float xf = xps[(16 + cc) * 36 + b];
            float xg = xps[(32 + cc) * 36 + b];
            float xo = xps[(48 + cc) * 36 + b];
#pragma unroll
            for (int k = 0; k < 4; k++) {
                const float* kb = kgb + k * (64 * 33);
                xi += kb[cc * 33 + b];
                xf += kb[(16 + cc) * 33 + b];
                xg += kb[(32 + cc) * 33 + b];
                xo += kb[(48 + cc) * 33 + b];
            }
            float ig = 1.f / (1.f + __expf(-xi));
            float fg = 1.f / (1.f + __expf(-xf));
            float gg = tanhf(xg);
            float og = 1.f / (1.f + __expf(-xo));
            c_new[e] = fg * c_reg[e] + ig * gg;
            c_reg[e] = c_new[e];
            h_val[e] = og * tanhf(c_new[e]);

            size_t hoff = (size_t)(dir * T_LEN + t) * (BATCH * DIM)
                        + (size_t)b * DIM + j0 + cc;
            g_hf[hoff] = __float2half_rn(h_val[e]);
        }

        __syncthreads();
        if (tid == 0) {
            __threadfence();
            atomicAdd(my_rel + s, 1);
        }

        // off-critical-path stores
#pragma unroll
        for (int e = 0; e < 2; e++) {
            int cell = tid + e * 256;
            int b = cell >> 4, cc = cell & 15;
            out[(size_t)t * (BATCH * 1024) + (size_t)b * 1024 + dir * DIM + j0 + cc] = h_val[e];
            if (s == T_LEN - 1) {
                hout[((size_t)dir * BATCH + b) * DIM + j0 + cc] = h_val[e];
                cout[((size_t)dir * BATCH + b) * DIM + j0 + cc] = c_new[e];
            }
        }
    }
}

// ---------------------------------------------------------------------------
// Fused persistent kernel: CTAs 0..63 recurrence, 64..147 split+GEMM workers.
// ---------------------------------------------------------------------------
__global__ __launch_bounds__(256, 1)
void fused_kernel(const float* __restrict__ x,
                  const float* __restrict__ h0,
                  const float* __restrict__ c0,
                  const float* __restrict__ Wih,
                  const float* __restrict__ Whh,
                  const float* __restrict__ bih,
                  const float* __restrict__ bhh,
                  float* __restrict__ out,
                  float* __restrict__ hout,
                  float* __restrict__ cout)
{
    extern __shared__ char smem[];
    const int cta = blockIdx.x;
    if (cta < NREC) {
        rec_body(smem, h0, c0, Whh, out, hout, cout, cta);
    } else {
        gemm_worker(smem, x, Wih, bih, bhh, cta - NREC);
    }
}

// ---------------------------------------------------------------------------
// launch
// ---------------------------------------------------------------------------
extern "C" void kernel_launch(void* const* d_in, const int* in_sizes, int n_in,
                              void* d_out, int out_size)
{
    (void)in_sizes; (void)n_in; (void)out_size;
    const float* x   = (const float*)d_in[0];
    const float* h0  = (const float*)d_in[1];
    const float* c0  = (const float*)d_in[2];
    const float* Wih = (const float*)d_in[3];
    const float* bih = (const float*)d_in[4];
    const float* Whh = (const float*)d_in[5];
    const float* bhh = (const float*)d_in[6];

    float* out  = (float*)d_out;
    float* hout = out + (size_t)T_LEN * BATCH * 1024;
    float* cout = hout + (size_t)2 * BATCH * DIM;

    init_sync_kernel<<<16, 256>>>();

    cudaFuncSetAttribute(fused_kernel,
                         cudaFuncAttributeMaxDynamicSharedMemorySize, SMEM_TOTAL);
    fused_kernel<<<NGRID, 256, SMEM_TOTAL>>>(x, h0, c0, Wih, Whh, bih, bhh,
                                             out, hout, cout);
}